// round 14
// baseline (speedup 1.0000x reference)
#include <cuda_runtime.h>
#include <cuda_bf16.h>
#include <cstdint>

#define BATCH 512
#define FEAT  512
#define NBLK  128
#define NTHR  512

#define KH_LEN 256                          // K per CTA (half)
#define AS_STR 264                          // 256 + 8 bf16 pad
#define A_BYTES (64 * AS_STR * 2)           // 33792
#define B_BYTES (64 * AS_STR * 2)           // 33792
#define SMEM_TOTAL (A_BYTES + B_BYTES)      // 67584

__device__ float g_S0[BATCH * BATCH];       // k in [0,256) partial S
__device__ float g_S1[BATCH * BATCH];       // k in [256,512) partial S
__device__ unsigned g_band[8];              // monotonic band counters (16/replay)
__device__ unsigned long long g_sum = 0;
__device__ unsigned g_done = 0;

#define SUM_SCALE 1073741824.0f             // 2^30
#define INV_SUM   (1.0 / 1073741824.0)

__global__ void __launch_bounds__(NTHR, 1) fused_kernel(const float* __restrict__ fs,
                                                        const float* __restrict__ ft,
                                                        float* __restrict__ out) {
    extern __shared__ __align__(16) char smem[];
    __nv_bfloat16 (*As)[AS_STR] = (__nv_bfloat16(*)[AS_STR])smem;
    __nv_bfloat16 (*Bs)[AS_STR] = (__nv_bfloat16(*)[AS_STR])(smem + A_BYTES);

    __shared__ float refs[4][8];
    __shared__ float wr[16][8];
    __shared__ unsigned band_base;

    const int tid   = threadIdx.x;
    const int bx    = blockIdx.x;           // 0..7 (nTile)
    const int by    = blockIdx.y;           // 0..7 (mTile band)
    const int kh    = blockIdx.z;           // 0..1 (K half)
    const int mTile = by * 64;
    const int nTile = bx * 64;
    const int kOff  = kh * KH_LEN;
    const int warp  = tid >> 5;
    const int lane  = tid & 31;
    const int wm    = warp & 3;
    const int wn    = warp >> 2;

    if (tid == 0) band_base = g_band[by];

    // ================= Stage A and B tiles: MLP-16 LDG burst, then cvt+STS ===
    {
        const int row = tid >> 6;            // 0..7 -> 8 row-pairs per thread
        const int c4  = tid & 63;            // float4 chunk within 256-col slab
        float4 buf[16];
        // 8 A chunks (rows row, row+8, ..., row+56) and 8 B chunks interleaved:
        #pragma unroll
        for (int v = 0; v < 8; v++) {
            buf[v]     = *(const float4*)(fs + (mTile + row + v * 8) * FEAT + kOff + c4 * 4);
            buf[v + 8] = *(const float4*)(ft + (nTile + row + v * 8) * FEAT + kOff + c4 * 4);
        }
        #pragma unroll
        for (int v = 0; v < 8; v++) {
            __nv_bfloat162 a0 = __floats2bfloat162_rn(buf[v].x, buf[v].y);
            __nv_bfloat162 a1 = __floats2bfloat162_rn(buf[v].z, buf[v].w);
            *(uint2*)&As[row + v * 8][c4 * 4] = make_uint2(*(uint32_t*)&a0, *(uint32_t*)&a1);
            __nv_bfloat162 b0 = __floats2bfloat162_rn(buf[v + 8].x, buf[v + 8].y);
            __nv_bfloat162 b1 = __floats2bfloat162_rn(buf[v + 8].z, buf[v + 8].w);
            *(uint2*)&Bs[row + v * 8][c4 * 4] = make_uint2(*(uint32_t*)&b0, *(uint32_t*)&b1);
        }
    }
    __syncthreads();

    // ================= Mainloop: 16 k16-steps per warp =======================
    float acc[2][4] = {};
    const int a_row = 16 * wm + (lane & 7) + ((lane >> 3) & 1) * 8;
    const int a_k8  = (lane >> 4) * 8;
    const int b_row = 16 * wn + (lane & 7) + (lane >> 4) * 8;
    const int b_k8  = ((lane >> 3) & 1) * 8;

    const uint32_t abase = (uint32_t)__cvta_generic_to_shared(&As[a_row][a_k8]);
    const uint32_t bbase = (uint32_t)__cvta_generic_to_shared(&Bs[b_row][b_k8]);

    #pragma unroll
    for (int kk = 0; kk < 16; kk++) {
        const uint32_t koff = kk * 32;       // 16 bf16 = 32 bytes per step
        uint32_t a0, a1, a2, a3, b0, b1, b2, b3;
        asm volatile("ldmatrix.sync.aligned.m8n8.x4.shared.b16 {%0,%1,%2,%3}, [%4];\n"
                     : "=r"(a0), "=r"(a1), "=r"(a2), "=r"(a3) : "r"(abase + koff));
        asm volatile("ldmatrix.sync.aligned.m8n8.x4.shared.b16 {%0,%1,%2,%3}, [%4];\n"
                     : "=r"(b0), "=r"(b1), "=r"(b2), "=r"(b3) : "r"(bbase + koff));
        asm volatile("mma.sync.aligned.m16n8k16.row.col.f32.bf16.bf16.f32 "
                     "{%0,%1,%2,%3}, {%4,%5,%6,%7}, {%8,%9}, {%0,%1,%2,%3};\n"
                     : "+f"(acc[0][0]), "+f"(acc[0][1]), "+f"(acc[0][2]), "+f"(acc[0][3])
                     : "r"(a0), "r"(a1), "r"(a2), "r"(a3), "r"(b0), "r"(b1));
        asm volatile("mma.sync.aligned.m16n8k16.row.col.f32.bf16.bf16.f32 "
                     "{%0,%1,%2,%3}, {%4,%5,%6,%7}, {%8,%9}, {%0,%1,%2,%3};\n"
                     : "+f"(acc[1][0]), "+f"(acc[1][1]), "+f"(acc[1][2]), "+f"(acc[1][3])
                     : "r"(a0), "r"(a1), "r"(a2), "r"(a3), "r"(b2), "r"(b3));
    }

    // ================= Epilogue: STG partial S to this K-half's buffer =======
    {
        const int g = lane >> 2, t = lane & 3;
        const int row0 = mTile + 16 * wm + g;
        float* dst = kh ? g_S1 : g_S0;
        #pragma unroll
        for (int h = 0; h < 2; h++) {
            const int col = nTile + 16 * wn + t * 2 + 8 * h;
            *(float2*)&dst[row0 * BATCH + col]       = make_float2(acc[h][0], acc[h][1]);
            *(float2*)&dst[(row0 + 8) * BATCH + col] = make_float2(acc[h][2], acc[h][3]);
        }
    }
    __syncthreads();

    // ================= Band-local barrier (16 CTAs: 8 bx x 2 kh) =============
    if (tid == 0) {
        __threadfence();
        atomicAdd(&g_band[by], 1u);
        const unsigned target = band_base + 16u;
        while ((int)(*(volatile unsigned*)&g_band[by] - target) < 0) {}
        __threadfence();
    }
    __syncthreads();

    // ================= Phase 2: 4 rows per CTA, 128 thr/row ==================
    const int row_l = tid >> 7;              // 0..3
    const int c     = tid & 127;             // float4 chunk of the 512-wide row
    const int r     = by * 64 + (kh * 8 + bx) * 4 + row_l;
    const float4 u0 = ((const float4*)(g_S0 + r * BATCH))[c];
    const float4 u1 = ((const float4*)(g_S1 + r * BATCH))[c];
    const float4 v  = make_float4(u0.x + u1.x, u0.y + u1.y, u0.z + u1.z, u0.w + u1.w);

    const int rc0 = (r & ~7) >> 2;
    if (c == rc0)     *(float4*)&refs[row_l][0] = v;
    if (c == rc0 + 1) *(float4*)&refs[row_l][4] = v;
    __syncthreads();

    float p[8];
    #pragma unroll
    for (int j = 0; j < 8; j++) p[j] = refs[row_l][j];

    float s8[8];
    #pragma unroll
    for (int j = 0; j < 8; j++) {
        s8[j] = fmaxf(v.x - p[j], 0.f) + fmaxf(v.y - p[j], 0.f)
              + fmaxf(v.z - p[j], 0.f) + fmaxf(v.w - p[j], 0.f);
    }
    #pragma unroll
    for (int o = 16; o > 0; o >>= 1)
        #pragma unroll
        for (int j = 0; j < 8; j++)
            s8[j] += __shfl_down_sync(0xffffffffu, s8[j], o);
    if (lane == 0) {
        #pragma unroll
        for (int j = 0; j < 8; j++) wr[warp][j] = s8[j];
    }
    __syncthreads();

    float ratio = 0.f;
    if (tid < 32) {
        const int rl = tid >> 3, j = tid & 7;
        const float rk = 1.f + wr[rl * 4][j] + wr[rl * 4 + 1][j]
                             + wr[rl * 4 + 2][j] + wr[rl * 4 + 3][j];
        const float pj = refs[rl][j];
        float ps = 0.f;
        #pragma unroll
        for (int k = 0; k < 8; k++) ps += fmaxf(refs[rl][k] - pj, 0.f);
        ratio = (1.f + ps) / rk;
        #pragma unroll
        for (int o = 16; o > 0; o >>= 1)
            ratio += __shfl_down_sync(0xffffffffu, ratio, o);
    }

    // ================= Deterministic fixed-point tail ========================
    if (tid == 0) {
        atomicAdd(&g_sum, (unsigned long long)llrintf(ratio * SUM_SCALE));
        __threadfence();
        const unsigned prev = atomicAdd(&g_done, 1);
        if (prev == NBLK - 1) {
            const unsigned long long tot = *((volatile unsigned long long*)&g_sum);
            out[0] = (float)(1.0 - ((double)tot * INV_SUM) * (1.0 / 4096.0));
            g_sum  = 0;
            g_done = 0;
        }
    }
}

extern "C" void kernel_launch(void* const* d_in, const int* in_sizes, int n_in,
                              void* d_out, int out_size) {
    const float* fs = (const float*)d_in[0];
    const float* ft = (const float*)d_in[1];
    float* out = (float*)d_out;

    cudaFuncSetAttribute(fused_kernel,
                         cudaFuncAttributeMaxDynamicSharedMemorySize, SMEM_TOTAL);
    fused_kernel<<<dim3(8, 8, 2), NTHR, SMEM_TOTAL>>>(fs, ft, out);
}

// round 16
// speedup vs baseline: 1.0200x; 1.0200x over previous
#include <cuda_runtime.h>
#include <cuda_bf16.h>
#include <cstdint>

#define BATCH 512
#define FEAT  512
#define NBLK  256
#define NTHR  256

#define KQ_LEN 128                          // K per CTA (quarter)
#define AS_STR 136                          // 128 + 8 bf16 pad (272B row, odd 16B multiple)
#define A_BYTES (64 * AS_STR * 2)           // 17408
#define B_BYTES (64 * AS_STR * 2)           // 17408
#define SMEM_TOTAL (A_BYTES + B_BYTES)      // 34816  (x2 CTAs = 70KB < 228KB)

__device__ float g_Sq[4][BATCH * BATCH];    // per-K-quarter partial S
__device__ unsigned g_band[8];              // monotonic band counters (32/replay)
__device__ unsigned long long g_sum = 0;
__device__ unsigned g_done = 0;

#define SUM_SCALE 1073741824.0f             // 2^30
#define INV_SUM   (1.0 / 1073741824.0)

__global__ void __launch_bounds__(NTHR, 2) fused_kernel(const float* __restrict__ fs,
                                                        const float* __restrict__ ft,
                                                        float* __restrict__ out) {
    extern __shared__ __align__(16) char smem[];
    __nv_bfloat16 (*As)[AS_STR] = (__nv_bfloat16(*)[AS_STR])smem;
    __nv_bfloat16 (*Bs)[AS_STR] = (__nv_bfloat16(*)[AS_STR])(smem + A_BYTES);

    __shared__ float refs[2][8];
    __shared__ float wr[8][8];
    __shared__ unsigned band_base;

    const int tid   = threadIdx.x;
    const int bx    = blockIdx.x;           // 0..7 (nTile)
    const int by    = blockIdx.y;           // 0..7 (mTile band)
    const int kh    = blockIdx.z;           // 0..3 (K quarter)
    const int mTile = by * 64;
    const int nTile = bx * 64;
    const int kOff  = kh * KQ_LEN;
    const int warp  = tid >> 5;
    const int lane  = tid & 31;
    const int wm    = warp & 3;              // 4(m) x 2(n) warp grid, warp tile 16x32
    const int wn    = warp >> 2;

    if (tid == 0) band_base = g_band[by];

    // ================= Stage A and B tiles (fp32 -> bf16) ====================
    // 64 rows x 128 cols = 2048 float4 chunks each; 8 per thread per tensor.
    {
        #pragma unroll 8
        for (int v = 0; v < 8; v++) {
            const int idx = tid + v * NTHR;
            const int row = idx >> 5;        // 0..63
            const int c4  = idx & 31;        // float4 chunk (128 floats/row)
            const float4 x = *(const float4*)(fs + (mTile + row) * FEAT + kOff + c4 * 4);
            __nv_bfloat162 h0 = __floats2bfloat162_rn(x.x, x.y);
            __nv_bfloat162 h1 = __floats2bfloat162_rn(x.z, x.w);
            *(uint2*)&As[row][c4 * 4] = make_uint2(*(uint32_t*)&h0, *(uint32_t*)&h1);
        }
        #pragma unroll 8
        for (int v = 0; v < 8; v++) {
            const int idx = tid + v * NTHR;
            const int row = idx >> 5;
            const int c4  = idx & 31;
            const float4 x = *(const float4*)(ft + (nTile + row) * FEAT + kOff + c4 * 4);
            __nv_bfloat162 h0 = __floats2bfloat162_rn(x.x, x.y);
            __nv_bfloat162 h1 = __floats2bfloat162_rn(x.z, x.w);
            *(uint2*)&Bs[row][c4 * 4] = make_uint2(*(uint32_t*)&h0, *(uint32_t*)&h1);
        }
    }
    __syncthreads();

    // ================= Mainloop: 8 k16-steps, warp tile 16x32 ================
    float acc[4][4] = {};                    // 4 n8-tiles at cols 32*wn + nt*8
    const int a_row = 16 * wm + (lane & 7) + ((lane >> 3) & 1) * 8;
    const int a_k8  = (lane >> 4) * 8;
    const int b_row = 32 * wn + (lane & 7) + (lane >> 4) * 8;
    const int b_k8  = ((lane >> 3) & 1) * 8;

    const uint32_t abase  = (uint32_t)__cvta_generic_to_shared(&As[a_row][a_k8]);
    const uint32_t bbase0 = (uint32_t)__cvta_generic_to_shared(&Bs[b_row][b_k8]);
    const uint32_t bbase1 = (uint32_t)__cvta_generic_to_shared(&Bs[b_row + 16][b_k8]);

    #pragma unroll
    for (int kk = 0; kk < 8; kk++) {
        const uint32_t koff = kk * 32;       // 16 bf16 = 32 B per step
        uint32_t a0, a1, a2, a3;
        uint32_t p0, p1, p2, p3, q0, q1, q2, q3;
        asm volatile("ldmatrix.sync.aligned.m8n8.x4.shared.b16 {%0,%1,%2,%3}, [%4];\n"
                     : "=r"(a0), "=r"(a1), "=r"(a2), "=r"(a3) : "r"(abase + koff));
        asm volatile("ldmatrix.sync.aligned.m8n8.x4.shared.b16 {%0,%1,%2,%3}, [%4];\n"
                     : "=r"(p0), "=r"(p1), "=r"(p2), "=r"(p3) : "r"(bbase0 + koff));
        asm volatile("ldmatrix.sync.aligned.m8n8.x4.shared.b16 {%0,%1,%2,%3}, [%4];\n"
                     : "=r"(q0), "=r"(q1), "=r"(q2), "=r"(q3) : "r"(bbase1 + koff));
        asm volatile("mma.sync.aligned.m16n8k16.row.col.f32.bf16.bf16.f32 "
                     "{%0,%1,%2,%3}, {%4,%5,%6,%7}, {%8,%9}, {%0,%1,%2,%3};\n"
                     : "+f"(acc[0][0]), "+f"(acc[0][1]), "+f"(acc[0][2]), "+f"(acc[0][3])
                     : "r"(a0), "r"(a1), "r"(a2), "r"(a3), "r"(p0), "r"(p1));
        asm volatile("mma.sync.aligned.m16n8k16.row.col.f32.bf16.bf16.f32 "
                     "{%0,%1,%2,%3}, {%4,%5,%6,%7}, {%8,%9}, {%0,%1,%2,%3};\n"
                     : "+f"(acc[1][0]), "+f"(acc[1][1]), "+f"(acc[1][2]), "+f"(acc[1][3])
                     : "r"(a0), "r"(a1), "r"(a2), "r"(a3), "r"(p2), "r"(p3));
        asm volatile("mma.sync.aligned.m16n8k16.row.col.f32.bf16.bf16.f32 "
                     "{%0,%1,%2,%3}, {%4,%5,%6,%7}, {%8,%9}, {%0,%1,%2,%3};\n"
                     : "+f"(acc[2][0]), "+f"(acc[2][1]), "+f"(acc[2][2]), "+f"(acc[2][3])
                     : "r"(a0), "r"(a1), "r"(a2), "r"(a3), "r"(q0), "r"(q1));
        asm volatile("mma.sync.aligned.m16n8k16.row.col.f32.bf16.bf16.f32 "
                     "{%0,%1,%2,%3}, {%4,%5,%6,%7}, {%8,%9}, {%0,%1,%2,%3};\n"
                     : "+f"(acc[3][0]), "+f"(acc[3][1]), "+f"(acc[3][2]), "+f"(acc[3][3])
                     : "r"(a0), "r"(a1), "r"(a2), "r"(a3), "r"(q2), "r"(q3));
    }

    // ================= Epilogue: STG partial S to this quarter's buffer ======
    {
        const int g = lane >> 2, t = lane & 3;
        const int row0 = mTile + 16 * wm + g;
        float* dst = g_Sq[kh];
        #pragma unroll
        for (int nt = 0; nt < 4; nt++) {
            const int col = nTile + 32 * wn + nt * 8 + t * 2;
            *(float2*)&dst[row0 * BATCH + col]       = make_float2(acc[nt][0], acc[nt][1]);
            *(float2*)&dst[(row0 + 8) * BATCH + col] = make_float2(acc[nt][2], acc[nt][3]);
        }
    }
    __syncthreads();

    // ================= Band-local barrier (32 CTAs: 8 bx x 4 kh) =============
    if (tid == 0) {
        __threadfence();
        atomicAdd(&g_band[by], 1u);
        const unsigned target = band_base + 32u;
        while ((int)(*(volatile unsigned*)&g_band[by] - target) < 0) {}
        __threadfence();
    }
    __syncthreads();

    // ================= Phase 2: 2 rows per CTA, 128 thr/row ==================
    const int row_l = tid >> 7;              // 0..1
    const int c     = tid & 127;             // float4 chunk of 512-wide row
    const int r     = by * 64 + (kh * 8 + bx) * 2 + row_l;
    const float4 q0 = ((const float4*)(g_Sq[0] + r * BATCH))[c];
    const float4 q1 = ((const float4*)(g_Sq[1] + r * BATCH))[c];
    const float4 q2 = ((const float4*)(g_Sq[2] + r * BATCH))[c];
    const float4 q3 = ((const float4*)(g_Sq[3] + r * BATCH))[c];
    const float4 v  = make_float4(((q0.x + q1.x) + q2.x) + q3.x,
                                  ((q0.y + q1.y) + q2.y) + q3.y,
                                  ((q0.z + q1.z) + q2.z) + q3.z,
                                  ((q0.w + q1.w) + q2.w) + q3.w);

    const int rc0 = (r & ~7) >> 2;
    if (c == rc0)     *(float4*)&refs[row_l][0] = v;
    if (c == rc0 + 1) *(float4*)&refs[row_l][4] = v;
    __syncthreads();

    float p[8];
    #pragma unroll
    for (int j = 0; j < 8; j++) p[j] = refs[row_l][j];

    float s8[8];
    #pragma unroll
    for (int j = 0; j < 8; j++) {
        s8[j] = fmaxf(v.x - p[j], 0.f) + fmaxf(v.y - p[j], 0.f)
              + fmaxf(v.z - p[j], 0.f) + fmaxf(v.w - p[j], 0.f);
    }
    #pragma unroll
    for (int o = 16; o > 0; o >>= 1)
        #pragma unroll
        for (int j = 0; j < 8; j++)
            s8[j] += __shfl_down_sync(0xffffffffu, s8[j], o);
    if (lane == 0) {
        #pragma unroll
        for (int j = 0; j < 8; j++) wr[warp][j] = s8[j];
    }
    __syncthreads();

    float ratio = 0.f;
    if (tid < 16) {
        const int rl = tid >> 3, j = tid & 7;
        const float rk = 1.f + wr[rl * 4][j] + wr[rl * 4 + 1][j]
                             + wr[rl * 4 + 2][j] + wr[rl * 4 + 3][j];
        const float pj = refs[rl][j];
        float ps = 0.f;
        #pragma unroll
        for (int k = 0; k < 8; k++) ps += fmaxf(refs[rl][k] - pj, 0.f);
        ratio = (1.f + ps) / rk;
        #pragma unroll
        for (int o = 8; o > 0; o >>= 1)
            ratio += __shfl_down_sync(0xffffffffu, ratio, o);
    }

    // ================= Deterministic fixed-point tail ========================
    if (tid == 0) {
        atomicAdd(&g_sum, (unsigned long long)llrintf(ratio * SUM_SCALE));
        __threadfence();
        const unsigned prev = atomicAdd(&g_done, 1);
        if (prev == NBLK - 1) {
            const unsigned long long tot = *((volatile unsigned long long*)&g_sum);
            out[0] = (float)(1.0 - ((double)tot * INV_SUM) * (1.0 / 4096.0));
            g_sum  = 0;
            g_done = 0;
        }
    }
}

extern "C" void kernel_launch(void* const* d_in, const int* in_sizes, int n_in,
                              void* d_out, int out_size) {
    const float* fs = (const float*)d_in[0];
    const float* ft = (const float*)d_in[1];
    float* out = (float*)d_out;

    cudaFuncSetAttribute(fused_kernel,
                         cudaFuncAttributeMaxDynamicSharedMemorySize, SMEM_TOTAL);
    fused_kernel<<<dim3(8, 8, 4), NTHR, SMEM_TOTAL>>>(fs, ft, out);
}

// round 17
// speedup vs baseline: 1.2179x; 1.1940x over previous
#include <cuda_runtime.h>
#include <cuda_bf16.h>
#include <cstdint>

#define BATCH 512
#define FEAT  512
#define NTHR  256
#define NBLK2 256

#define KQ_LEN 128
#define AS_STR 136                          // 128 + 8 bf16 pad
#define A_BYTES (64 * AS_STR * 2)           // 17408
#define B_BYTES (64 * AS_STR * 2)           // 17408
#define SMEM_TOTAL (A_BYTES + B_BYTES)      // 34816

__device__ float g_Sq[4][BATCH * BATCH];    // per-K-quarter partial S
__device__ unsigned long long g_sum = 0;
__device__ unsigned g_done = 0;

#define SUM_SCALE 1073741824.0f             // 2^30
#define INV_SUM   (1.0 / 1073741824.0)

// ---------------------------------------------------------------------------
// Kernel 1: bf16 HMMA GEMM, 64x64 tile, K quarter per CTA. No inter-CTA sync.
// Grid (8, 8, 4) = 256 CTAs, 256 threads, 2 CTAs/SM.
// ---------------------------------------------------------------------------
__global__ void __launch_bounds__(NTHR, 2) gemm_kernel(const float* __restrict__ fs,
                                                       const float* __restrict__ ft) {
    extern __shared__ __align__(16) char smem[];
    __nv_bfloat16 (*As)[AS_STR] = (__nv_bfloat16(*)[AS_STR])smem;
    __nv_bfloat16 (*Bs)[AS_STR] = (__nv_bfloat16(*)[AS_STR])(smem + A_BYTES);

    const int tid   = threadIdx.x;
    const int mTile = blockIdx.y * 64;
    const int nTile = blockIdx.x * 64;
    const int kh    = blockIdx.z;
    const int kOff  = kh * KQ_LEN;
    const int warp  = tid >> 5;
    const int lane  = tid & 31;
    const int wm    = warp & 3;
    const int wn    = warp >> 2;

    // ---- Stage A and B tiles (fp32 -> bf16) ----
    #pragma unroll 8
    for (int v = 0; v < 8; v++) {
        const int idx = tid + v * NTHR;
        const int row = idx >> 5, c4 = idx & 31;
        const float4 x = *(const float4*)(fs + (mTile + row) * FEAT + kOff + c4 * 4);
        __nv_bfloat162 h0 = __floats2bfloat162_rn(x.x, x.y);
        __nv_bfloat162 h1 = __floats2bfloat162_rn(x.z, x.w);
        *(uint2*)&As[row][c4 * 4] = make_uint2(*(uint32_t*)&h0, *(uint32_t*)&h1);
    }
    #pragma unroll 8
    for (int v = 0; v < 8; v++) {
        const int idx = tid + v * NTHR;
        const int row = idx >> 5, c4 = idx & 31;
        const float4 x = *(const float4*)(ft + (nTile + row) * FEAT + kOff + c4 * 4);
        __nv_bfloat162 h0 = __floats2bfloat162_rn(x.x, x.y);
        __nv_bfloat162 h1 = __floats2bfloat162_rn(x.z, x.w);
        *(uint2*)&Bs[row][c4 * 4] = make_uint2(*(uint32_t*)&h0, *(uint32_t*)&h1);
    }
    __syncthreads();

    // ---- Mainloop: 8 k16-steps, warp tile 16x32 ----
    float acc[4][4] = {};
    const int a_row = 16 * wm + (lane & 7) + ((lane >> 3) & 1) * 8;
    const int a_k8  = (lane >> 4) * 8;
    const int b_row = 32 * wn + (lane & 7) + (lane >> 4) * 8;
    const int b_k8  = ((lane >> 3) & 1) * 8;

    const uint32_t abase  = (uint32_t)__cvta_generic_to_shared(&As[a_row][a_k8]);
    const uint32_t bbase0 = (uint32_t)__cvta_generic_to_shared(&Bs[b_row][b_k8]);
    const uint32_t bbase1 = (uint32_t)__cvta_generic_to_shared(&Bs[b_row + 16][b_k8]);

    #pragma unroll
    for (int kk = 0; kk < 8; kk++) {
        const uint32_t koff = kk * 32;
        uint32_t a0, a1, a2, a3;
        uint32_t p0, p1, p2, p3, q0, q1, q2, q3;
        asm volatile("ldmatrix.sync.aligned.m8n8.x4.shared.b16 {%0,%1,%2,%3}, [%4];\n"
                     : "=r"(a0), "=r"(a1), "=r"(a2), "=r"(a3) : "r"(abase + koff));
        asm volatile("ldmatrix.sync.aligned.m8n8.x4.shared.b16 {%0,%1,%2,%3}, [%4];\n"
                     : "=r"(p0), "=r"(p1), "=r"(p2), "=r"(p3) : "r"(bbase0 + koff));
        asm volatile("ldmatrix.sync.aligned.m8n8.x4.shared.b16 {%0,%1,%2,%3}, [%4];\n"
                     : "=r"(q0), "=r"(q1), "=r"(q2), "=r"(q3) : "r"(bbase1 + koff));
        asm volatile("mma.sync.aligned.m16n8k16.row.col.f32.bf16.bf16.f32 "
                     "{%0,%1,%2,%3}, {%4,%5,%6,%7}, {%8,%9}, {%0,%1,%2,%3};\n"
                     : "+f"(acc[0][0]), "+f"(acc[0][1]), "+f"(acc[0][2]), "+f"(acc[0][3])
                     : "r"(a0), "r"(a1), "r"(a2), "r"(a3), "r"(p0), "r"(p1));
        asm volatile("mma.sync.aligned.m16n8k16.row.col.f32.bf16.bf16.f32 "
                     "{%0,%1,%2,%3}, {%4,%5,%6,%7}, {%8,%9}, {%0,%1,%2,%3};\n"
                     : "+f"(acc[1][0]), "+f"(acc[1][1]), "+f"(acc[1][2]), "+f"(acc[1][3])
                     : "r"(a0), "r"(a1), "r"(a2), "r"(a3), "r"(p2), "r"(p3));
        asm volatile("mma.sync.aligned.m16n8k16.row.col.f32.bf16.bf16.f32 "
                     "{%0,%1,%2,%3}, {%4,%5,%6,%7}, {%8,%9}, {%0,%1,%2,%3};\n"
                     : "+f"(acc[2][0]), "+f"(acc[2][1]), "+f"(acc[2][2]), "+f"(acc[2][3])
                     : "r"(a0), "r"(a1), "r"(a2), "r"(a3), "r"(q0), "r"(q1));
        asm volatile("mma.sync.aligned.m16n8k16.row.col.f32.bf16.bf16.f32 "
                     "{%0,%1,%2,%3}, {%4,%5,%6,%7}, {%8,%9}, {%0,%1,%2,%3};\n"
                     : "+f"(acc[3][0]), "+f"(acc[3][1]), "+f"(acc[3][2]), "+f"(acc[3][3])
                     : "r"(a0), "r"(a1), "r"(a2), "r"(a3), "r"(q2), "r"(q3));
    }

    // ---- Epilogue: STG partial S to this quarter's buffer ----
    const int g = lane >> 2, t = lane & 3;
    const int row0 = mTile + 16 * wm + g;
    float* dst = g_Sq[kh];
    #pragma unroll
    for (int nt = 0; nt < 4; nt++) {
        const int col = nTile + 32 * wn + nt * 8 + t * 2;
        *(float2*)&dst[row0 * BATCH + col]       = make_float2(acc[nt][0], acc[nt][1]);
        *(float2*)&dst[(row0 + 8) * BATCH + col] = make_float2(acc[nt][2], acc[nt][3]);
    }
}

// ---------------------------------------------------------------------------
// Kernel 2: phase 2 — 2 rows per CTA, 128 threads/row; fixed-point tail.
// Grid 256 CTAs x 256 threads. No spin barriers anywhere.
// ---------------------------------------------------------------------------
__global__ void __launch_bounds__(NTHR, 2) phase2_kernel(float* __restrict__ out) {
    __shared__ float refs[2][8];
    __shared__ float wr[8][8];

    const int tid   = threadIdx.x;
    const int warp  = tid >> 5;
    const int lane  = tid & 31;
    const int row_l = tid >> 7;              // 0..1
    const int c     = tid & 127;             // float4 chunk
    const int r     = blockIdx.x * 2 + row_l;

    const float4 q0 = ((const float4*)(g_Sq[0] + r * BATCH))[c];
    const float4 q1 = ((const float4*)(g_Sq[1] + r * BATCH))[c];
    const float4 q2 = ((const float4*)(g_Sq[2] + r * BATCH))[c];
    const float4 q3 = ((const float4*)(g_Sq[3] + r * BATCH))[c];
    const float4 v  = make_float4(((q0.x + q1.x) + q2.x) + q3.x,
                                  ((q0.y + q1.y) + q2.y) + q3.y,
                                  ((q0.z + q1.z) + q2.z) + q3.z,
                                  ((q0.w + q1.w) + q2.w) + q3.w);

    const int rc0 = (r & ~7) >> 2;
    if (c == rc0)     *(float4*)&refs[row_l][0] = v;
    if (c == rc0 + 1) *(float4*)&refs[row_l][4] = v;
    __syncthreads();

    float p[8];
    #pragma unroll
    for (int j = 0; j < 8; j++) p[j] = refs[row_l][j];

    float s8[8];
    #pragma unroll
    for (int j = 0; j < 8; j++) {
        s8[j] = fmaxf(v.x - p[j], 0.f) + fmaxf(v.y - p[j], 0.f)
              + fmaxf(v.z - p[j], 0.f) + fmaxf(v.w - p[j], 0.f);
    }
    #pragma unroll
    for (int o = 16; o > 0; o >>= 1)
        #pragma unroll
        for (int j = 0; j < 8; j++)
            s8[j] += __shfl_down_sync(0xffffffffu, s8[j], o);
    if (lane == 0) {
        #pragma unroll
        for (int j = 0; j < 8; j++) wr[warp][j] = s8[j];
    }
    __syncthreads();

    float ratio = 0.f;
    if (tid < 16) {
        const int rl = tid >> 3, j = tid & 7;
        const float rk = 1.f + wr[rl * 4][j] + wr[rl * 4 + 1][j]
                             + wr[rl * 4 + 2][j] + wr[rl * 4 + 3][j];
        const float pj = refs[rl][j];
        float ps = 0.f;
        #pragma unroll
        for (int k = 0; k < 8; k++) ps += fmaxf(refs[rl][k] - pj, 0.f);
        ratio = (1.f + ps) / rk;
        #pragma unroll
        for (int o = 8; o > 0; o >>= 1)
            ratio += __shfl_down_sync(0xffffffffu, ratio, o);
    }

    if (tid == 0) {
        atomicAdd(&g_sum, (unsigned long long)llrintf(ratio * SUM_SCALE));
        __threadfence();
        const unsigned prev = atomicAdd(&g_done, 1);
        if (prev == NBLK2 - 1) {
            const unsigned long long tot = *((volatile unsigned long long*)&g_sum);
            out[0] = (float)(1.0 - ((double)tot * INV_SUM) * (1.0 / 4096.0));
            g_sum  = 0;
            g_done = 0;
        }
    }
}

extern "C" void kernel_launch(void* const* d_in, const int* in_sizes, int n_in,
                              void* d_out, int out_size) {
    const float* fs = (const float*)d_in[0];
    const float* ft = (const float*)d_in[1];
    float* out = (float*)d_out;

    cudaFuncSetAttribute(gemm_kernel,
                         cudaFuncAttributeMaxDynamicSharedMemorySize, SMEM_TOTAL);
    gemm_kernel<<<dim3(8, 8, 4), NTHR, SMEM_TOTAL>>>(fs, ft);
    phase2_kernel<<<NBLK2, NTHR>>>(out);
}